// round 3
// baseline (speedup 1.0000x reference)
#include <cuda_runtime.h>

#define BROWS 32768
#define DDIM  1024
#define NCHUNK 64          // row chunks for column stats
#define CHUNK  512         // rows per chunk (64*512 = 32768)

// Scratch (static device globals: allocation-free per harness rules)
__device__ float g_h[(size_t)BROWS * DDIM];          // 128 MB GEMM output
__device__ float g_psum[NCHUNK * DDIM];
__device__ float g_psq[NCHUNK * DDIM];
__device__ float g_scale[DDIM];
__device__ float g_shift[DDIM];

// ---------------------------------------------------------------------------
// Kernel 1: g_h = A[B,D] * W[D,D]^T + bias   (both A and W are K-major)
// 128x128 block tile, BK=16, 256 threads, 8x8 microtile per thread.
// ---------------------------------------------------------------------------
#define BM 128
#define BN 128
#define BK 16

__global__ __launch_bounds__(256, 2)
void gemm_kernel(const float* __restrict__ A, const float* __restrict__ W,
                 const float* __restrict__ bias) {
    __shared__ float As[BK][BM];
    __shared__ float Ws[BK][BN];

    const int bx  = blockIdx.x;   // col tile (0..7)
    const int by  = blockIdx.y;   // row tile (0..255)
    const int tid = threadIdx.x;
    const int tx  = tid & 15;
    const int ty  = tid >> 4;

    const float* Ab = A + (size_t)by * BM * DDIM;
    const float* Wb = W + (size_t)bx * BN * DDIM;

    float acc[8][8];
    #pragma unroll
    for (int i = 0; i < 8; i++) {
        #pragma unroll
        for (int j = 0; j < 8; j++) acc[i][j] = 0.f;
    }

    for (int k0 = 0; k0 < DDIM; k0 += BK) {
        // Load tiles: 512 float4 per operand, 2 per thread, linear mapping so a
        // warp covers 8 full 64B row-segments (full sector utilization).
        #pragma unroll
        for (int l = 0; l < 2; l++) {
            int v   = l * 256 + tid;   // 0..511
            int row = v >> 2;          // 0..127
            int kq  = (v & 3) << 2;    // 0,4,8,12
            float4 fa = *(const float4*)(Ab + (size_t)row * DDIM + k0 + kq);
            As[kq + 0][row] = fa.x; As[kq + 1][row] = fa.y;
            As[kq + 2][row] = fa.z; As[kq + 3][row] = fa.w;
            float4 fw = *(const float4*)(Wb + (size_t)row * DDIM + k0 + kq);
            Ws[kq + 0][row] = fw.x; Ws[kq + 1][row] = fw.y;
            Ws[kq + 2][row] = fw.z; Ws[kq + 3][row] = fw.w;
        }
        __syncthreads();

        #pragma unroll
        for (int k = 0; k < BK; k++) {
            float4 a0 = *(const float4*)&As[k][ty * 4];
            float4 a1 = *(const float4*)&As[k][64 + ty * 4];
            float4 b0 = *(const float4*)&Ws[k][tx * 4];
            float4 b1 = *(const float4*)&Ws[k][64 + tx * 4];
            float af[8] = {a0.x, a0.y, a0.z, a0.w, a1.x, a1.y, a1.z, a1.w};
            float bf[8] = {b0.x, b0.y, b0.z, b0.w, b1.x, b1.y, b1.z, b1.w};
            #pragma unroll
            for (int i = 0; i < 8; i++) {
                #pragma unroll
                for (int j = 0; j < 8; j++)
                    acc[i][j] = fmaf(af[i], bf[j], acc[i][j]);
            }
        }
        __syncthreads();
    }

    const int c0 = bx * BN + tx * 4;
    float4 bv0 = *(const float4*)(bias + c0);
    float4 bv1 = *(const float4*)(bias + c0 + 64);
    #pragma unroll
    for (int i = 0; i < 8; i++) {
        int row = by * BM + ((i < 4) ? (ty * 4 + i) : (64 + ty * 4 + i - 4));
        float* out = g_h + (size_t)row * DDIM + c0;
        float4 o0 = make_float4(acc[i][0] + bv0.x, acc[i][1] + bv0.y,
                                acc[i][2] + bv0.z, acc[i][3] + bv0.w);
        float4 o1 = make_float4(acc[i][4] + bv1.x, acc[i][5] + bv1.y,
                                acc[i][6] + bv1.z, acc[i][7] + bv1.w);
        *(float4*)out = o0;
        *(float4*)(out + 64) = o1;
    }
}

// ---------------------------------------------------------------------------
// Kernel 2: per-column partial sums / sums of squares (deterministic, no atomics)
// grid: (32 colgroups, 64 rowchunks), 256 threads = 32 cols x 8 rows
// ---------------------------------------------------------------------------
__global__ __launch_bounds__(256)
void colstats_kernel() {
    const int lane = threadIdx.x & 31;
    const int ty   = threadIdx.x >> 5;             // 0..7
    const int col  = blockIdx.x * 32 + lane;
    const int r0   = blockIdx.y * CHUNK;

    float s = 0.f, q = 0.f;
    for (int r = ty; r < CHUNK; r += 8) {
        float v = g_h[(size_t)(r0 + r) * DDIM + col];
        s += v;
        q = fmaf(v, v, q);
    }
    __shared__ float sh_s[8][32];
    __shared__ float sh_q[8][32];
    sh_s[ty][lane] = s;
    sh_q[ty][lane] = q;
    __syncthreads();
    if (ty == 0) {
        #pragma unroll
        for (int i = 1; i < 8; i++) { s += sh_s[i][lane]; q += sh_q[i][lane]; }
        g_psum[blockIdx.y * DDIM + col] = s;
        g_psq [blockIdx.y * DDIM + col] = q;
    }
}

// ---------------------------------------------------------------------------
// Kernel 3: finalize BN stats -> per-column affine (scale, shift)
// ---------------------------------------------------------------------------
__global__ void finalize_stats(const float* __restrict__ gamma,
                               const float* __restrict__ beta) {
    int j = blockIdx.x * blockDim.x + threadIdx.x;
    if (j >= DDIM) return;
    float s = 0.f, q = 0.f;
    for (int c = 0; c < NCHUNK; c++) {
        s += g_psum[c * DDIM + j];
        q += g_psq [c * DDIM + j];
    }
    const float invB = 1.0f / (float)BROWS;
    float mean = s * invB;
    float var  = fmaf(-mean, mean, q * invB);      // biased variance
    float sc   = gamma[j] * rsqrtf(var + 1e-5f);
    g_scale[j] = sc;
    g_shift[j] = fmaf(-mean, sc, beta[j]);
}

// ---------------------------------------------------------------------------
// Kernel 4: z = p * BN(h); sparsemax via Michelot fixed-point; write output.
// One block per row, 256 threads x 4 values in registers.
// ---------------------------------------------------------------------------
__global__ __launch_bounds__(256)
void sparsemax_kernel(const float* __restrict__ P, float* __restrict__ O) {
    const int r    = blockIdx.x;
    const int t    = threadIdx.x;
    const int c    = t * 4;
    const int lane = t & 31;
    const int warp = t >> 5;

    float4 hv = *(const float4*)(g_h + (size_t)r * DDIM + c);
    float4 pv = *(const float4*)(P   + (size_t)r * DDIM + c);
    float4 sc = *(const float4*)(g_scale + c);
    float4 sh = *(const float4*)(g_shift + c);

    float z[4];
    z[0] = pv.x * fmaf(hv.x, sc.x, sh.x);
    z[1] = pv.y * fmaf(hv.y, sc.y, sh.y);
    z[2] = pv.z * fmaf(hv.z, sc.z, sh.z);
    z[3] = pv.w * fmaf(hv.w, sc.w, sh.w);

    __shared__ float red_s[8];
    __shared__ float red_k[8];
    __shared__ float bc_tau;
    __shared__ float bc_k;

    float tau   = -1e30f;   // first iteration = full active set
    float prevk = -1.f;

    for (int it = 0; it < 48; it++) {
        float s = 0.f, kf = 0.f;
        #pragma unroll
        for (int i = 0; i < 4; i++) {
            if (z[i] > tau) { s += z[i]; kf += 1.f; }
        }
        #pragma unroll
        for (int o = 16; o > 0; o >>= 1) {
            s  += __shfl_xor_sync(0xffffffffu, s,  o);
            kf += __shfl_xor_sync(0xffffffffu, kf, o);
        }
        if (lane == 0) { red_s[warp] = s; red_k[warp] = kf; }
        __syncthreads();
        if (t == 0) {
            float S = 0.f, K = 0.f;
            #pragma unroll
            for (int w = 0; w < 8; w++) { S += red_s[w]; K += red_k[w]; }
            bc_tau = (S - 1.f) / K;
            bc_k   = K;
        }
        __syncthreads();
        tau = bc_tau;
        float K = bc_k;
        if (K == prevk) break;   // support unchanged -> converged
        prevk = K;
    }

    float4 o;
    o.x = fmaxf(z[0] - tau, 0.f);
    o.y = fmaxf(z[1] - tau, 0.f);
    o.z = fmaxf(z[2] - tau, 0.f);
    o.w = fmaxf(z[3] - tau, 0.f);
    *(float4*)(O + (size_t)r * DDIM + c) = o;
}

// ---------------------------------------------------------------------------
extern "C" void kernel_launch(void* const* d_in, const int* in_sizes, int n_in,
                              void* d_out, int out_size) {
    const float* a     = (const float*)d_in[0];
    const float* p     = (const float*)d_in[1];
    const float* W     = (const float*)d_in[2];
    const float* b     = (const float*)d_in[3];
    const float* gamma = (const float*)d_in[4];
    const float* beta  = (const float*)d_in[5];
    float* out = (float*)d_out;

    dim3 g1(DDIM / BN, BROWS / BM);      // (8, 256)
    gemm_kernel<<<g1, 256>>>(a, W, b);

    dim3 g2(DDIM / 32, NCHUNK);          // (32, 64)
    colstats_kernel<<<g2, 256>>>();

    finalize_stats<<<4, 256>>>(gamma, beta);

    sparsemax_kernel<<<BROWS, 256>>>(p, out);
}

// round 5
// speedup vs baseline: 1.8356x; 1.8356x over previous
#include <cuda_runtime.h>
#include <cuda_fp16.h>
#include <cstdint>

#define BROWS 32768
#define DDIM  1024
#define NCHUNK 64
#define CHUNK  512

// ---------------- scratch (static device globals; allocation-free) ----------
__device__ float g_h[(size_t)BROWS * DDIM];      // 128 MB GEMM output
__device__ __half g_Ahi[(size_t)BROWS * DDIM];   // 64 MB
__device__ __half g_Alo[(size_t)BROWS * DDIM];   // 64 MB
__device__ __half g_Whi[(size_t)DDIM * DDIM];    // 2 MB
__device__ __half g_Wlo[(size_t)DDIM * DDIM];    // 2 MB
__device__ float g_psum[NCHUNK * DDIM];
__device__ float g_psq[NCHUNK * DDIM];
__device__ float g_scale[DDIM];
__device__ float g_shift[DDIM];

// ---------------- PTX helpers (baseline PTX only: sm_80-class) --------------
__device__ __forceinline__ uint32_t smem_u32(const void* p) {
    uint32_t a;
    asm("{ .reg .u64 t; cvta.to.shared.u64 t, %1; cvt.u32.u64 %0, t; }"
        : "=r"(a) : "l"(p));
    return a;
}
#define CP_ASYNC16(dst, src) \
    asm volatile("cp.async.cg.shared.global [%0], [%1], 16;" :: "r"(dst), "l"(src))
#define CP_COMMIT() asm volatile("cp.async.commit_group;" ::: "memory")
#define CP_WAIT1()  asm volatile("cp.async.wait_group 1;" ::: "memory")
#define CP_WAIT0()  asm volatile("cp.async.wait_group 0;" ::: "memory")

#define LDSM_X4(R0, R1, R2, R3, ADDR) \
    asm volatile("ldmatrix.sync.aligned.m8n8.x4.shared.b16 {%0,%1,%2,%3}, [%4];" \
        : "=r"(R0), "=r"(R1), "=r"(R2), "=r"(R3) : "r"(ADDR))

#define MMA16816(C, A, B0, B1) \
    asm volatile("mma.sync.aligned.m16n8k16.row.col.f32.f16.f16.f32 " \
        "{%0,%1,%2,%3}, {%4,%5,%6,%7}, {%8,%9}, {%0,%1,%2,%3};" \
        : "+f"((C)[0]), "+f"((C)[1]), "+f"((C)[2]), "+f"((C)[3]) \
        : "r"((A)[0]), "r"((A)[1]), "r"((A)[2]), "r"((A)[3]), "r"(B0), "r"(B1))

// ---------------- Kernel 0: fp32 -> (fp16 hi, fp16 lo) split ----------------
__global__ __launch_bounds__(256)
void convertA_kernel(const float* __restrict__ src) {
    size_t i = ((size_t)blockIdx.x * 256 + threadIdx.x) * 4;
    float4 v = *(const float4*)(src + i);
    float xs[4] = {v.x, v.y, v.z, v.w};
    __half h[4], l[4];
    #pragma unroll
    for (int j = 0; j < 4; j++) {
        h[j] = __float2half_rn(xs[j]);
        l[j] = __float2half_rn(xs[j] - __half2float(h[j]));
    }
    __half2 h0; h0.x = h[0]; h0.y = h[1];
    __half2 h1; h1.x = h[2]; h1.y = h[3];
    __half2 l0; l0.x = l[0]; l0.y = l[1];
    __half2 l1; l1.x = l[2]; l1.y = l[3];
    *(__half2*)(g_Ahi + i)     = h0;
    *(__half2*)(g_Ahi + i + 2) = h1;
    *(__half2*)(g_Alo + i)     = l0;
    *(__half2*)(g_Alo + i + 2) = l1;
}
__global__ __launch_bounds__(256)
void convertW_kernel(const float* __restrict__ src) {
    size_t i = ((size_t)blockIdx.x * 256 + threadIdx.x) * 4;
    float4 v = *(const float4*)(src + i);
    float xs[4] = {v.x, v.y, v.z, v.w};
    __half h[4], l[4];
    #pragma unroll
    for (int j = 0; j < 4; j++) {
        h[j] = __float2half_rn(xs[j]);
        l[j] = __float2half_rn(xs[j] - __half2float(h[j]));
    }
    __half2 h0; h0.x = h[0]; h0.y = h[1];
    __half2 h1; h1.x = h[2]; h1.y = h[3];
    __half2 l0; l0.x = l[0]; l0.y = l[1];
    __half2 l1; l1.x = l[2]; l1.y = l[3];
    *(__half2*)(g_Whi + i)     = h0;
    *(__half2*)(g_Whi + i + 2) = h1;
    *(__half2*)(g_Wlo + i)     = l0;
    *(__half2*)(g_Wlo + i + 2) = l1;
}

// ---------------- Kernel 1: HMMA fp16x3 GEMM --------------------------------
// C[B,1024] = A @ W^T + bias. 128x128x32 CTA tile, 8 warps (4x2), 3-stage
// cp.async. Per-stage SMEM: Ahi|Alo|Whi|Wlo, each 128 rows x 32 halves,
// row stride 40 halves (80B) for conflict-free ldmatrix.
#define BM 128
#define BN 128
#define BK 32
#define NKCH (DDIM / BK)            // 32
#define LDS 40                      // halves per SMEM row (80 bytes)
#define TILE_B (128 * LDS * 2)      // 10240 bytes per matrix tile
#define STAGE_B (4 * TILE_B)        // 40960 bytes per stage
#define SMEM_TOTAL (3 * STAGE_B)    // 122880 bytes

__global__ __launch_bounds__(256, 1)
void gemm_hmma_kernel(const float* __restrict__ bias) {
    extern __shared__ __align__(16) __half smem[];
    const uint32_t sbase = smem_u32(smem);

    const int tid  = threadIdx.x;
    const int wid  = tid >> 5;
    const int lane = tid & 31;
    const int wm   = wid & 3;              // warp m index (0..3) -> 32 rows
    const int wn   = wid >> 2;             // warp n index (0..1) -> 64 cols
    const int m0g  = blockIdx.y * BM;
    const int n0g  = blockIdx.x * BN;

    // ldmatrix per-thread addressing
    const int g = lane >> 3, r = lane & 7;
    // A groups: row = (g&1)*8 + r, col = (g>>1)*8
    const uint32_t a_off = (uint32_t)((wm * 32 + (g & 1) * 8 + r) * LDS + (g >> 1) * 8) * 2;
    // B groups: row = (g>>1)*8 + r, col = (g&1)*8
    const uint32_t b_off = (uint32_t)((wn * 64 + (g >> 1) * 8 + r) * LDS + (g & 1) * 8) * 2;

    float acc[2][8][4];
    #pragma unroll
    for (int i = 0; i < 2; i++)
        #pragma unroll
        for (int j = 0; j < 8; j++)
            #pragma unroll
            for (int q = 0; q < 4; q++) acc[i][j][q] = 0.f;

    // stage loader: 4 matrices x 128 rows x 64B, 8 cp.async/thread
    auto load_stage = [&](int s, int c) {
        const int k0 = c * BK;
        const uint32_t base = sbase + s * STAGE_B;
        #pragma unroll
        for (int i = 0; i < 2; i++) {
            int v = i * 256 + tid;
            int row = v >> 2, seg = v & 3;
            uint32_t doff = (uint32_t)(row * LDS * 2 + seg * 16);
            const __half* pAh = g_Ahi + (size_t)(m0g + row) * DDIM + k0 + seg * 8;
            const __half* pAl = g_Alo + (size_t)(m0g + row) * DDIM + k0 + seg * 8;
            const __half* pWh = g_Whi + (size_t)(n0g + row) * DDIM + k0 + seg * 8;
            const __half* pWl = g_Wlo + (size_t)(n0g + row) * DDIM + k0 + seg * 8;
            CP_ASYNC16(base + doff,              pAh);
            CP_ASYNC16(base + TILE_B + doff,     pAl);
            CP_ASYNC16(base + 2 * TILE_B + doff, pWh);
            CP_ASYNC16(base + 3 * TILE_B + doff, pWl);
        }
    };

    load_stage(0, 0); CP_COMMIT();
    load_stage(1, 1); CP_COMMIT();

    for (int c = 0; c < NKCH; c++) {
        if (c < NKCH - 1) { CP_WAIT1(); } else { CP_WAIT0(); }
        __syncthreads();
        if (c + 2 < NKCH) { load_stage((c + 2) % 3, c + 2); CP_COMMIT(); }

        const uint32_t sb  = sbase + (c % 3) * STAGE_B;
        const uint32_t aHb = sb + a_off;
        const uint32_t aLb = sb + TILE_B + a_off;
        const uint32_t bHb = sb + 2 * TILE_B + b_off;
        const uint32_t bLb = sb + 3 * TILE_B + b_off;

        #pragma unroll
        for (int ks = 0; ks < BK; ks += 16) {
            uint32_t aH[2][4], aL[2][4];
            #pragma unroll
            for (int mt = 0; mt < 2; mt++) {
                LDSM_X4(aH[mt][0], aH[mt][1], aH[mt][2], aH[mt][3],
                        aHb + mt * (16 * LDS * 2) + ks * 2);
                LDSM_X4(aL[mt][0], aL[mt][1], aL[mt][2], aL[mt][3],
                        aLb + mt * (16 * LDS * 2) + ks * 2);
            }
            #pragma unroll
            for (int h = 0; h < 2; h++) {
                uint32_t bH[4][2], bL[4][2];
                #pragma unroll
                for (int tp = 0; tp < 2; tp++) {
                    uint32_t off = (h * 32 + tp * 16) * (LDS * 2) + ks * 2;
                    LDSM_X4(bH[2 * tp][0], bH[2 * tp][1],
                            bH[2 * tp + 1][0], bH[2 * tp + 1][1], bHb + off);
                    LDSM_X4(bL[2 * tp][0], bL[2 * tp][1],
                            bL[2 * tp + 1][0], bL[2 * tp + 1][1], bLb + off);
                }
                #pragma unroll
                for (int mt = 0; mt < 2; mt++) {
                    #pragma unroll
                    for (int nt = 0; nt < 4; nt++) {
                        float* C = acc[mt][h * 4 + nt];
                        MMA16816(C, aH[mt], bH[nt][0], bH[nt][1]);
                        MMA16816(C, aH[mt], bL[nt][0], bL[nt][1]);
                        MMA16816(C, aL[mt], bH[nt][0], bH[nt][1]);
                    }
                }
            }
        }
    }

    // epilogue: add bias, store fp32 to g_h
    #pragma unroll
    for (int mt = 0; mt < 2; mt++) {
        const int row0 = m0g + wm * 32 + mt * 16 + (lane >> 2);
        #pragma unroll
        for (int j = 0; j < 8; j++) {
            const int col = n0g + wn * 64 + j * 8 + 2 * (lane & 3);
            float2 bv = *(const float2*)(bias + col);
            float* p0 = g_h + (size_t)row0 * DDIM + col;
            float* p1 = p0 + 8 * DDIM;
            float2 o0 = make_float2(acc[mt][j][0] + bv.x, acc[mt][j][1] + bv.y);
            float2 o1 = make_float2(acc[mt][j][2] + bv.x, acc[mt][j][3] + bv.y);
            *(float2*)p0 = o0;
            *(float2*)p1 = o1;
        }
    }
}

// ---------------- Kernel 2: per-column partial stats ------------------------
__global__ __launch_bounds__(256)
void colstats_kernel() {
    const int lane = threadIdx.x & 31;
    const int ty   = threadIdx.x >> 5;
    const int col  = blockIdx.x * 32 + lane;
    const int r0   = blockIdx.y * CHUNK;

    float s = 0.f, q = 0.f;
    for (int r = ty; r < CHUNK; r += 8) {
        float v = g_h[(size_t)(r0 + r) * DDIM + col];
        s += v;
        q = fmaf(v, v, q);
    }
    __shared__ float sh_s[8][32];
    __shared__ float sh_q[8][32];
    sh_s[ty][lane] = s;
    sh_q[ty][lane] = q;
    __syncthreads();
    if (ty == 0) {
        #pragma unroll
        for (int i = 1; i < 8; i++) { s += sh_s[i][lane]; q += sh_q[i][lane]; }
        g_psum[blockIdx.y * DDIM + col] = s;
        g_psq [blockIdx.y * DDIM + col] = q;
    }
}

// ---------------- Kernel 3: finalize BN stats -------------------------------
__global__ void finalize_stats(const float* __restrict__ gamma,
                               const float* __restrict__ beta) {
    int j = blockIdx.x * blockDim.x + threadIdx.x;
    if (j >= DDIM) return;
    float s = 0.f, q = 0.f;
    for (int c = 0; c < NCHUNK; c++) {
        s += g_psum[c * DDIM + j];
        q += g_psq [c * DDIM + j];
    }
    const float invB = 1.0f / (float)BROWS;
    float mean = s * invB;
    float var  = fmaf(-mean, mean, q * invB);
    float sc   = gamma[j] * rsqrtf(var + 1e-5f);
    g_scale[j] = sc;
    g_shift[j] = fmaf(-mean, sc, beta[j]);
}

// ---------------- Kernel 4: sparsemax (Michelot fixed-point) ----------------
__global__ __launch_bounds__(256)
void sparsemax_kernel(const float* __restrict__ P, float* __restrict__ O) {
    const int r    = blockIdx.x;
    const int t    = threadIdx.x;
    const int c    = t * 4;
    const int lane = t & 31;
    const int warp = t >> 5;

    float4 hv = *(const float4*)(g_h + (size_t)r * DDIM + c);
    float4 pv = *(const float4*)(P   + (size_t)r * DDIM + c);
    float4 sc = *(const float4*)(g_scale + c);
    float4 sh = *(const float4*)(g_shift + c);

    float z[4];
    z[0] = pv.x * fmaf(hv.x, sc.x, sh.x);
    z[1] = pv.y * fmaf(hv.y, sc.y, sh.y);
    z[2] = pv.z * fmaf(hv.z, sc.z, sh.z);
    z[3] = pv.w * fmaf(hv.w, sc.w, sh.w);

    __shared__ float red_s[8];
    __shared__ float red_k[8];
    __shared__ float bc_tau;
    __shared__ float bc_k;

    float tau   = -1e30f;
    float prevk = -1.f;

    for (int it = 0; it < 48; it++) {
        float s = 0.f, kf = 0.f;
        #pragma unroll
        for (int i = 0; i < 4; i++) {
            if (z[i] > tau) { s += z[i]; kf += 1.f; }
        }
        #pragma unroll
        for (int o = 16; o > 0; o >>= 1) {
            s  += __shfl_xor_sync(0xffffffffu, s,  o);
            kf += __shfl_xor_sync(0xffffffffu, kf, o);
        }
        if (lane == 0) { red_s[warp] = s; red_k[warp] = kf; }
        __syncthreads();
        if (t == 0) {
            float S = 0.f, K = 0.f;
            #pragma unroll
            for (int w = 0; w < 8; w++) { S += red_s[w]; K += red_k[w]; }
            bc_tau = (S - 1.f) / K;
            bc_k   = K;
        }
        __syncthreads();
        tau = bc_tau;
        float K = bc_k;
        if (K == prevk) break;
        prevk = K;
    }

    float4 o;
    o.x = fmaxf(z[0] - tau, 0.f);
    o.y = fmaxf(z[1] - tau, 0.f);
    o.z = fmaxf(z[2] - tau, 0.f);
    o.w = fmaxf(z[3] - tau, 0.f);
    *(float4*)(O + (size_t)r * DDIM + c) = o;
}

// ---------------------------------------------------------------------------
extern "C" void kernel_launch(void* const* d_in, const int* in_sizes, int n_in,
                              void* d_out, int out_size) {
    const float* a     = (const float*)d_in[0];
    const float* p     = (const float*)d_in[1];
    const float* W     = (const float*)d_in[2];
    const float* b     = (const float*)d_in[3];
    const float* gamma = (const float*)d_in[4];
    const float* beta  = (const float*)d_in[5];
    float* out = (float*)d_out;

    cudaFuncSetAttribute(gemm_hmma_kernel,
                         cudaFuncAttributeMaxDynamicSharedMemorySize, SMEM_TOTAL);

    convertA_kernel<<<(BROWS * DDIM) / (256 * 4), 256>>>(a);
    convertW_kernel<<<(DDIM * DDIM) / (256 * 4), 256>>>(W);

    dim3 g1(DDIM / BN, BROWS / BM);                // (8, 256)
    gemm_hmma_kernel<<<g1, 256, SMEM_TOTAL>>>(b);

    dim3 g2(DDIM / 32, NCHUNK);                    // (32, 64)
    colstats_kernel<<<g2, 256>>>();

    finalize_stats<<<4, 256>>>(gamma, beta);

    sparsemax_kernel<<<BROWS, 256>>>(p, out);
}

// round 6
// speedup vs baseline: 2.0238x; 1.1025x over previous
#include <cuda_runtime.h>
#include <cuda_fp16.h>
#include <cstdint>

#define BROWS 32768
#define DDIM  1024
#define NCHUNK 64
#define CHUNK  512

// ---------------- scratch (static device globals; allocation-free) ----------
__device__ float g_h[(size_t)BROWS * DDIM];      // 128 MB GEMM output
__device__ __half g_Ahi[(size_t)BROWS * DDIM];   // 64 MB
__device__ __half g_Alo[(size_t)BROWS * DDIM];   // 64 MB
__device__ __half g_Whi[(size_t)DDIM * DDIM];    // 2 MB
__device__ __half g_Wlo[(size_t)DDIM * DDIM];    // 2 MB
__device__ float g_psum[NCHUNK * DDIM];
__device__ float g_psq[NCHUNK * DDIM];
__device__ float g_scale[DDIM];
__device__ float g_shift[DDIM];

// ---------------- PTX helpers (baseline PTX only: sm_80-class) --------------
__device__ __forceinline__ uint32_t smem_u32(const void* p) {
    uint32_t a;
    asm("{ .reg .u64 t; cvta.to.shared.u64 t, %1; cvt.u32.u64 %0, t; }"
        : "=r"(a) : "l"(p));
    return a;
}
#define CP_ASYNC16(dst, src) \
    asm volatile("cp.async.cg.shared.global [%0], [%1], 16;" :: "r"(dst), "l"(src))
#define CP_COMMIT() asm volatile("cp.async.commit_group;" ::: "memory")
#define CP_WAIT1()  asm volatile("cp.async.wait_group 1;" ::: "memory")
#define CP_WAIT0()  asm volatile("cp.async.wait_group 0;" ::: "memory")

#define LDSM_X4(R0, R1, R2, R3, ADDR) \
    asm volatile("ldmatrix.sync.aligned.m8n8.x4.shared.b16 {%0,%1,%2,%3}, [%4];" \
        : "=r"(R0), "=r"(R1), "=r"(R2), "=r"(R3) : "r"(ADDR))

#define MMA16816(C, A, B0, B1) \
    asm volatile("mma.sync.aligned.m16n8k16.row.col.f32.f16.f16.f32 " \
        "{%0,%1,%2,%3}, {%4,%5,%6,%7}, {%8,%9}, {%0,%1,%2,%3};" \
        : "+f"((C)[0]), "+f"((C)[1]), "+f"((C)[2]), "+f"((C)[3]) \
        : "r"((A)[0]), "r"((A)[1]), "r"((A)[2]), "r"((A)[3]), "r"(B0), "r"(B1))

// ---------------- Kernel 0: fp32 -> (fp16 hi, fp16 lo) split ----------------
__global__ __launch_bounds__(256)
void convertA_kernel(const float* __restrict__ src) {
    size_t i = ((size_t)blockIdx.x * 256 + threadIdx.x) * 4;
    float4 v = *(const float4*)(src + i);
    float xs[4] = {v.x, v.y, v.z, v.w};
    __half h[4], l[4];
    #pragma unroll
    for (int j = 0; j < 4; j++) {
        h[j] = __float2half_rn(xs[j]);
        l[j] = __float2half_rn(xs[j] - __half2float(h[j]));
    }
    __half2 h0; h0.x = h[0]; h0.y = h[1];
    __half2 h1; h1.x = h[2]; h1.y = h[3];
    __half2 l0; l0.x = l[0]; l0.y = l[1];
    __half2 l1; l1.x = l[2]; l1.y = l[3];
    *(__half2*)(g_Ahi + i)     = h0;
    *(__half2*)(g_Ahi + i + 2) = h1;
    *(__half2*)(g_Alo + i)     = l0;
    *(__half2*)(g_Alo + i + 2) = l1;
}
__global__ __launch_bounds__(256)
void convertW_kernel(const float* __restrict__ src) {
    size_t i = ((size_t)blockIdx.x * 256 + threadIdx.x) * 4;
    float4 v = *(const float4*)(src + i);
    float xs[4] = {v.x, v.y, v.z, v.w};
    __half h[4], l[4];
    #pragma unroll
    for (int j = 0; j < 4; j++) {
        h[j] = __float2half_rn(xs[j]);
        l[j] = __float2half_rn(xs[j] - __half2float(h[j]));
    }
    __half2 h0; h0.x = h[0]; h0.y = h[1];
    __half2 h1; h1.x = h[2]; h1.y = h[3];
    __half2 l0; l0.x = l[0]; l0.y = l[1];
    __half2 l1; l1.x = l[2]; l1.y = l[3];
    *(__half2*)(g_Whi + i)     = h0;
    *(__half2*)(g_Whi + i + 2) = h1;
    *(__half2*)(g_Wlo + i)     = l0;
    *(__half2*)(g_Wlo + i + 2) = l1;
}

// ---------------- Kernel 1: HMMA fp16x3 GEMM --------------------------------
// C[B,1024] = A @ W^T + bias. 128x128x32 CTA tile, 8 warps (4x2), 3-stage
// cp.async. Per-stage SMEM: Ahi|Alo|Whi|Wlo, each 128 rows x 32 halves,
// row stride 40 halves (80B) for conflict-free ldmatrix.
#define BM 128
#define BN 128
#define BK 32
#define NKCH (DDIM / BK)            // 32
#define LDS 40                      // halves per SMEM row (80 bytes)
#define TILE_B (128 * LDS * 2)      // 10240 bytes per matrix tile
#define STAGE_B (4 * TILE_B)        // 40960 bytes per stage
#define SMEM_TOTAL (3 * STAGE_B)    // 122880 bytes

__global__ __launch_bounds__(256, 1)
void gemm_hmma_kernel(const float* __restrict__ bias) {
    extern __shared__ __align__(16) __half smem[];
    const uint32_t sbase = smem_u32(smem);

    const int tid  = threadIdx.x;
    const int wid  = tid >> 5;
    const int lane = tid & 31;
    const int wm   = wid & 3;              // warp m index (0..3) -> 32 rows
    const int wn   = wid >> 2;             // warp n index (0..1) -> 64 cols
    const int m0g  = blockIdx.y * BM;
    const int n0g  = blockIdx.x * BN;

    // ldmatrix per-thread addressing
    const int g = lane >> 3, r = lane & 7;
    const uint32_t a_off = (uint32_t)((wm * 32 + (g & 1) * 8 + r) * LDS + (g >> 1) * 8) * 2;
    const uint32_t b_off = (uint32_t)((wn * 64 + (g >> 1) * 8 + r) * LDS + (g & 1) * 8) * 2;

    float acc[2][8][4];
    #pragma unroll
    for (int i = 0; i < 2; i++)
        #pragma unroll
        for (int j = 0; j < 8; j++)
            #pragma unroll
            for (int q = 0; q < 4; q++) acc[i][j][q] = 0.f;

    auto load_stage = [&](int s, int c) {
        const int k0 = c * BK;
        const uint32_t base = sbase + s * STAGE_B;
        #pragma unroll
        for (int i = 0; i < 2; i++) {
            int v = i * 256 + tid;
            int row = v >> 2, seg = v & 3;
            uint32_t doff = (uint32_t)(row * LDS * 2 + seg * 16);
            const __half* pAh = g_Ahi + (size_t)(m0g + row) * DDIM + k0 + seg * 8;
            const __half* pAl = g_Alo + (size_t)(m0g + row) * DDIM + k0 + seg * 8;
            const __half* pWh = g_Whi + (size_t)(n0g + row) * DDIM + k0 + seg * 8;
            const __half* pWl = g_Wlo + (size_t)(n0g + row) * DDIM + k0 + seg * 8;
            CP_ASYNC16(base + doff,              pAh);
            CP_ASYNC16(base + TILE_B + doff,     pAl);
            CP_ASYNC16(base + 2 * TILE_B + doff, pWh);
            CP_ASYNC16(base + 3 * TILE_B + doff, pWl);
        }
    };

    load_stage(0, 0); CP_COMMIT();
    load_stage(1, 1); CP_COMMIT();

    for (int c = 0; c < NKCH; c++) {
        if (c < NKCH - 1) { CP_WAIT1(); } else { CP_WAIT0(); }
        __syncthreads();
        if (c + 2 < NKCH) { load_stage((c + 2) % 3, c + 2); CP_COMMIT(); }

        const uint32_t sb  = sbase + (c % 3) * STAGE_B;
        const uint32_t aHb = sb + a_off;
        const uint32_t aLb = sb + TILE_B + a_off;
        const uint32_t bHb = sb + 2 * TILE_B + b_off;
        const uint32_t bLb = sb + 3 * TILE_B + b_off;

        #pragma unroll
        for (int ks = 0; ks < BK; ks += 16) {
            uint32_t aH[2][4], aL[2][4];
            #pragma unroll
            for (int mt = 0; mt < 2; mt++) {
                LDSM_X4(aH[mt][0], aH[mt][1], aH[mt][2], aH[mt][3],
                        aHb + mt * (16 * LDS * 2) + ks * 2);
                LDSM_X4(aL[mt][0], aL[mt][1], aL[mt][2], aL[mt][3],
                        aLb + mt * (16 * LDS * 2) + ks * 2);
            }
            #pragma unroll
            for (int h = 0; h < 2; h++) {
                uint32_t bH[4][2], bL[4][2];
                #pragma unroll
                for (int tp = 0; tp < 2; tp++) {
                    uint32_t off = (h * 32 + tp * 16) * (LDS * 2) + ks * 2;
                    LDSM_X4(bH[2 * tp][0], bH[2 * tp][1],
                            bH[2 * tp + 1][0], bH[2 * tp + 1][1], bHb + off);
                    LDSM_X4(bL[2 * tp][0], bL[2 * tp][1],
                            bL[2 * tp + 1][0], bL[2 * tp + 1][1], bLb + off);
                }
                #pragma unroll
                for (int mt = 0; mt < 2; mt++) {
                    #pragma unroll
                    for (int nt = 0; nt < 4; nt++) {
                        float* C = acc[mt][h * 4 + nt];
                        MMA16816(C, aH[mt], bH[nt][0], bH[nt][1]);
                        MMA16816(C, aH[mt], bL[nt][0], bL[nt][1]);
                        MMA16816(C, aL[mt], bH[nt][0], bH[nt][1]);
                    }
                }
            }
        }
    }

    // epilogue: add bias, store fp32 to g_h
    #pragma unroll
    for (int mt = 0; mt < 2; mt++) {
        const int row0 = m0g + wm * 32 + mt * 16 + (lane >> 2);
        #pragma unroll
        for (int j = 0; j < 8; j++) {
            const int col = n0g + wn * 64 + j * 8 + 2 * (lane & 3);
            float2 bv = *(const float2*)(bias + col);
            float* p0 = g_h + (size_t)row0 * DDIM + col;
            float* p1 = p0 + 8 * DDIM;
            float2 o0 = make_float2(acc[mt][j][0] + bv.x, acc[mt][j][1] + bv.y);
            float2 o1 = make_float2(acc[mt][j][2] + bv.x, acc[mt][j][3] + bv.y);
            *(float2*)p0 = o0;
            *(float2*)p1 = o1;
        }
    }
}

// ---------------- Kernel 2: per-column partial stats ------------------------
__global__ __launch_bounds__(256)
void colstats_kernel() {
    const int lane = threadIdx.x & 31;
    const int ty   = threadIdx.x >> 5;
    const int col  = blockIdx.x * 32 + lane;
    const int r0   = blockIdx.y * CHUNK;

    float s = 0.f, q = 0.f;
    for (int r = ty; r < CHUNK; r += 8) {
        float v = g_h[(size_t)(r0 + r) * DDIM + col];
        s += v;
        q = fmaf(v, v, q);
    }
    __shared__ float sh_s[8][32];
    __shared__ float sh_q[8][32];
    sh_s[ty][lane] = s;
    sh_q[ty][lane] = q;
    __syncthreads();
    if (ty == 0) {
        #pragma unroll
        for (int i = 1; i < 8; i++) { s += sh_s[i][lane]; q += sh_q[i][lane]; }
        g_psum[blockIdx.y * DDIM + col] = s;
        g_psq [blockIdx.y * DDIM + col] = q;
    }
}

// ---------------- Kernel 3: finalize BN stats -------------------------------
__global__ void finalize_stats(const float* __restrict__ gamma,
                               const float* __restrict__ beta) {
    int j = blockIdx.x * blockDim.x + threadIdx.x;
    if (j >= DDIM) return;
    float s = 0.f, q = 0.f;
    for (int c = 0; c < NCHUNK; c++) {
        s += g_psum[c * DDIM + j];
        q += g_psq [c * DDIM + j];
    }
    const float invB = 1.0f / (float)BROWS;
    float mean = s * invB;
    float var  = fmaf(-mean, mean, q * invB);
    float sc   = gamma[j] * rsqrtf(var + 1e-5f);
    g_scale[j] = sc;
    g_shift[j] = fmaf(-mean, sc, beta[j]);
}

// ---------------- Kernel 4: sparsemax, warp-per-row (no block syncs) --------
// 32 values per lane in registers; Michelot tau iteration fully in-warp via
// butterfly shuffles (every lane ends with S and K -> computes tau locally).
__global__ __launch_bounds__(256)
void sparsemax_kernel(const float* __restrict__ P, float* __restrict__ O) {
    const int warp = threadIdx.x >> 5;
    const int lane = threadIdx.x & 31;
    const int r    = blockIdx.x * 8 + warp;

    const float* hrow = g_h + (size_t)r * DDIM;
    const float* prow = P   + (size_t)r * DDIM;

    float z[32];
    #pragma unroll
    for (int i = 0; i < 8; i++) {
        const int c = i * 128 + lane * 4;
        float4 hv = *(const float4*)(hrow + c);
        float4 pv = *(const float4*)(prow + c);
        float4 sc = *(const float4*)(g_scale + c);
        float4 sh = *(const float4*)(g_shift + c);
        z[i * 4 + 0] = pv.x * fmaf(hv.x, sc.x, sh.x);
        z[i * 4 + 1] = pv.y * fmaf(hv.y, sc.y, sh.y);
        z[i * 4 + 2] = pv.z * fmaf(hv.z, sc.z, sh.z);
        z[i * 4 + 3] = pv.w * fmaf(hv.w, sc.w, sh.w);
    }

    float tau   = -1e30f;    // first iteration = full active set
    float prevk = -1.f;
    for (int it = 0; it < 48; it++) {
        float s = 0.f, kf = 0.f;
        #pragma unroll
        for (int i = 0; i < 32; i++) {
            if (z[i] > tau) { s += z[i]; kf += 1.f; }
        }
        #pragma unroll
        for (int o = 16; o > 0; o >>= 1) {
            s  += __shfl_xor_sync(0xffffffffu, s,  o);
            kf += __shfl_xor_sync(0xffffffffu, kf, o);
        }
        tau = (s - 1.f) / kf;
        if (kf == prevk) break;       // support fixed -> converged (warp-uniform)
        prevk = kf;
    }

    float* orow = O + (size_t)r * DDIM;
    #pragma unroll
    for (int i = 0; i < 8; i++) {
        const int c = i * 128 + lane * 4;
        float4 o;
        o.x = fmaxf(z[i * 4 + 0] - tau, 0.f);
        o.y = fmaxf(z[i * 4 + 1] - tau, 0.f);
        o.z = fmaxf(z[i * 4 + 2] - tau, 0.f);
        o.w = fmaxf(z[i * 4 + 3] - tau, 0.f);
        *(float4*)(orow + c) = o;
    }
}

// ---------------------------------------------------------------------------
extern "C" void kernel_launch(void* const* d_in, const int* in_sizes, int n_in,
                              void* d_out, int out_size) {
    const float* a     = (const float*)d_in[0];
    const float* p     = (const float*)d_in[1];
    const float* W     = (const float*)d_in[2];
    const float* b     = (const float*)d_in[3];
    const float* gamma = (const float*)d_in[4];
    const float* beta  = (const float*)d_in[5];
    float* out = (float*)d_out;

    cudaFuncSetAttribute(gemm_hmma_kernel,
                         cudaFuncAttributeMaxDynamicSharedMemorySize, SMEM_TOTAL);

    convertA_kernel<<<(BROWS * DDIM) / (256 * 4), 256>>>(a);
    convertW_kernel<<<(DDIM * DDIM) / (256 * 4), 256>>>(W);

    dim3 g1(DDIM / BN, BROWS / BM);                // (8, 256)
    gemm_hmma_kernel<<<g1, 256, SMEM_TOTAL>>>(b);

    dim3 g2(DDIM / 32, NCHUNK);                    // (32, 64)
    colstats_kernel<<<g2, 256>>>();

    finalize_stats<<<4, 256>>>(gamma, beta);

    sparsemax_kernel<<<BROWS / 8, 256>>>(p, out);
}